// round 4
// baseline (speedup 1.0000x reference)
#include <cuda_runtime.h>
#include <cuda_bf16.h>
#include <math.h>

typedef __nv_bfloat16 bf16;

#define SEQ   2048
#define HID   4096
#define NQH   32
#define NKVH  8
#define HD    128
#define KVD   1024
#define QKVN  6144   // 4096 + 2*1024
#define KPAD  40     // padded smem row length (bf16 elems) -> conflict-free frags

// ------------------------- device scratch (no allocation allowed) ----------
__device__ __align__(16) bf16 g_hid_hi[(size_t)SEQ * HID];
__device__ __align__(16) bf16 g_hid_lo[(size_t)SEQ * HID];
__device__ __align__(16) bf16 g_wqkv_hi[(size_t)HID * QKVN];
__device__ __align__(16) bf16 g_wqkv_lo[(size_t)HID * QKVN];
__device__ __align__(16) bf16 g_wproj_hi[(size_t)HID * HID];
__device__ __align__(16) bf16 g_wproj_lo[(size_t)HID * HID];
__device__ __align__(16) float g_qkv[(size_t)SEQ * QKVN];
__device__ __align__(16) bf16 g_qkv_hi[(size_t)SEQ * QKVN];
__device__ __align__(16) bf16 g_qkv_lo[(size_t)SEQ * QKVN];
__device__ __align__(16) float g_scores[(size_t)NQH * SEQ * SEQ];
__device__ __align__(16) bf16 g_p_hi[(size_t)NQH * SEQ * SEQ];
__device__ __align__(16) bf16 g_p_lo[(size_t)NQH * SEQ * SEQ];
__device__ __align__(16) float g_attn[(size_t)SEQ * HID];
__device__ __align__(16) bf16 g_attn_hi[(size_t)SEQ * HID];
__device__ __align__(16) bf16 g_attn_lo[(size_t)SEQ * HID];

// ------------------------- helpers -----------------------------------------
__device__ __forceinline__ void mma16816(float* c, const unsigned* a, const unsigned* b)
{
    asm volatile(
        "mma.sync.aligned.m16n8k16.row.col.f32.bf16.bf16.f32 "
        "{%0,%1,%2,%3}, {%4,%5,%6,%7}, {%8,%9}, {%0,%1,%2,%3};\n"
        : "+f"(c[0]), "+f"(c[1]), "+f"(c[2]), "+f"(c[3])
        : "r"(a[0]), "r"(a[1]), "r"(a[2]), "r"(a[3]), "r"(b[0]), "r"(b[1]));
}

// ------------------------- split fp32 -> (hi, lo) bf16 ---------------------
__global__ void split_f32(const float* __restrict__ in,
                          bf16* __restrict__ hi, bf16* __restrict__ lo, size_t n)
{
    size_t i = ((size_t)blockIdx.x * blockDim.x + threadIdx.x) * 4;
    if (i >= n) return;
    float4 v = *(const float4*)(in + i);
    bf16 h0 = __float2bfloat16(v.x), h1 = __float2bfloat16(v.y);
    bf16 h2 = __float2bfloat16(v.z), h3 = __float2bfloat16(v.w);
    bf16 l0 = __float2bfloat16(v.x - __bfloat162float(h0));
    bf16 l1 = __float2bfloat16(v.y - __bfloat162float(h1));
    bf16 l2 = __float2bfloat16(v.z - __bfloat162float(h2));
    bf16 l3 = __float2bfloat16(v.w - __bfloat162float(h3));
    hi[i] = h0; hi[i+1] = h1; hi[i+2] = h2; hi[i+3] = h3;
    lo[i] = l0; lo[i+1] = l1; lo[i+2] = l2; lo[i+3] = l3;
}

// ---------------------------------------------------------------------------
// Triple-product bf16 GEMM: C = scale*(Ah*Bh + Ah*Bl + Al*Bh) + bias
// A: [M,K] row-major (K inner). B: if BTRANS, [K,N] row-major (transposed
// into smem); else [N,K] row-major (direct).
// Block 128x128, BK=32, 256 threads (8 warps, 2x4, 64x32 per warp).
// ---------------------------------------------------------------------------
template<bool BTRANS, bool CAUSAL>
__global__ __launch_bounds__(256) void gemm3(
    int M, int N, int K,
    const bf16* __restrict__ Ahi, const bf16* __restrict__ Alo, int lda, long long strideAz,
    const bf16* __restrict__ Bhi, const bf16* __restrict__ Blo, int ldb, long long strideBz, int bGroup,
    const float* __restrict__ bias, float scale,
    float* __restrict__ C, int ldc, long long strideCz)
{
    const int bx = blockIdx.x, by = blockIdx.y, bz = blockIdx.z;
    if (CAUSAL && bx > by) return;  // fully-masked tile, never read downstream

    __shared__ __align__(16) bf16 As[128][KPAD];
    __shared__ __align__(16) bf16 Bs[128][KPAD];

    const bf16* Ah = Ahi + (size_t)bz * strideAz;
    const bf16* Al = Alo + (size_t)bz * strideAz;
    const bf16* Bh = Bhi + (size_t)(bz / bGroup) * strideBz;
    const bf16* Bl = Blo + (size_t)(bz / bGroup) * strideBz;
    float* Cb = C + (size_t)bz * strideCz + (size_t)by * 128 * ldc + (size_t)bx * 128;

    const int tid  = threadIdx.x;
    const int warp = tid >> 5, lane = tid & 31;
    const int wm = warp >> 2, wn = warp & 3;       // 2 x 4 warp grid
    const int g = lane >> 2, t = lane & 3;

    // global load mapping
    const int aRow0 = tid >> 2, aRow1 = aRow0 + 64;
    const int aKc   = (tid & 3) * 8;
    // trans-B mapping
    const int bK0 = tid >> 4, bK1 = bK0 + 16;
    const int bNc = (tid & 15) * 8;

    const int kIters = K >> 5;
    const int nIter  = 3 * kIters;

    float acc[4][4][4];
#pragma unroll
    for (int i = 0; i < 4; i++)
#pragma unroll
        for (int j = 0; j < 4; j++)
#pragma unroll
            for (int q = 0; q < 4; q++) acc[i][j][q] = 0.f;

    uint4 rA0, rA1, rB0, rB1;

    auto loadTiles = [&](int it) {
        const int ph = it / kIters;
        const int kk = (it - ph * kIters) * 32;
        const bf16* pA = (ph == 2) ? Al : Ah;
        const bf16* pB = (ph == 1) ? Bl : Bh;
        const bf16* aB = pA + (size_t)(by * 128) * lda + kk;
        rA0 = *(const uint4*)(aB + (size_t)aRow0 * lda + aKc);
        rA1 = *(const uint4*)(aB + (size_t)aRow1 * lda + aKc);
        if (BTRANS) {
            const bf16* bB = pB + (size_t)bx * 128;
            rB0 = *(const uint4*)(bB + (size_t)(kk + bK0) * ldb + bNc);
            rB1 = *(const uint4*)(bB + (size_t)(kk + bK1) * ldb + bNc);
        } else {
            const bf16* bB = pB + (size_t)(bx * 128) * ldb + kk;
            rB0 = *(const uint4*)(bB + (size_t)aRow0 * ldb + aKc);
            rB1 = *(const uint4*)(bB + (size_t)aRow1 * ldb + aKc);
        }
    };

    loadTiles(0);

    for (int it = 0; it < nIter; it++) {
        // regs -> smem
        *(uint4*)&As[aRow0][aKc] = rA0;
        *(uint4*)&As[aRow1][aKc] = rA1;
        if (BTRANS) {
            const bf16* v0 = (const bf16*)&rB0;
            const bf16* v1 = (const bf16*)&rB1;
#pragma unroll
            for (int i = 0; i < 8; i++) Bs[bNc + i][bK0] = v0[i];
#pragma unroll
            for (int i = 0; i < 8; i++) Bs[bNc + i][bK1] = v1[i];
        } else {
            *(uint4*)&Bs[aRow0][aKc] = rB0;
            *(uint4*)&Bs[aRow1][aKc] = rB1;
        }
        __syncthreads();

        if (it + 1 < nIter) loadTiles(it + 1);

        // compute: 2 k-steps of 16, 4x4 m16n8k16 tiles per warp
#pragma unroll
        for (int ks = 0; ks < 2; ks++) {
            unsigned a[4][4], b[4][2];
            const int c0 = ks * 16 + 2 * t;
#pragma unroll
            for (int mt = 0; mt < 4; mt++) {
                const int r0 = wm * 64 + mt * 16 + g;
                a[mt][0] = *(const unsigned*)&As[r0][c0];
                a[mt][1] = *(const unsigned*)&As[r0 + 8][c0];
                a[mt][2] = *(const unsigned*)&As[r0][c0 + 8];
                a[mt][3] = *(const unsigned*)&As[r0 + 8][c0 + 8];
            }
#pragma unroll
            for (int nt = 0; nt < 4; nt++) {
                const int n = wn * 32 + nt * 8 + g;
                b[nt][0] = *(const unsigned*)&Bs[n][c0];
                b[nt][1] = *(const unsigned*)&Bs[n][c0 + 8];
            }
#pragma unroll
            for (int mt = 0; mt < 4; mt++)
#pragma unroll
                for (int nt = 0; nt < 4; nt++)
                    mma16816(acc[mt][nt], a[mt], b[nt]);
        }
        __syncthreads();
    }

    // epilogue
#pragma unroll
    for (int mt = 0; mt < 4; mt++) {
        const int r = wm * 64 + mt * 16 + g;
#pragma unroll
        for (int nt = 0; nt < 4; nt++) {
            const int cl = wn * 32 + nt * 8 + 2 * t;
            float b0 = 0.f, b1 = 0.f;
            if (bias) {
                const int gcol = bx * 128 + cl;
                b0 = bias[gcol]; b1 = bias[gcol + 1];
            }
            float2 v0 = make_float2(acc[mt][nt][0] * scale + b0,
                                    acc[mt][nt][1] * scale + b1);
            float2 v1 = make_float2(acc[mt][nt][2] * scale + b0,
                                    acc[mt][nt][3] * scale + b1);
            *(float2*)(Cb + (size_t)r * ldc + cl) = v0;
            *(float2*)(Cb + (size_t)(r + 8) * ldc + cl) = v1;
        }
    }
}

// ------------------------- RoPE (in-place, fp32 qkv) ------------------------
__global__ void rope_kernel(const int* __restrict__ positions)
{
    const int total = SEQ * 40 * 64;
    int idx = blockIdx.x * blockDim.x + threadIdx.x;
    if (idx >= total) return;
    const int i    = idx & 63;
    const int head = (idx >> 6) % 40;   // 0..31 Q, 32..39 K
    const int s    = idx / (40 * 64);

    float* base = g_qkv + (size_t)s * QKVN +
                  (head < 32 ? head * HD : HID + (head - 32) * HD);

    const double pos = (double)positions[s];
    const double inv_freq = exp(-(double)i * (9.210340371976184 / 64.0));
    const double a = pos * inv_freq;
    const float c  = (float)cos(a);
    const float sn = (float)sin(a);

    const float x1 = base[i];
    const float x2 = base[i + 64];
    base[i]      = x1 * c - x2 * sn;
    base[i + 64] = x2 * c + x1 * sn;
}

// ------------------------- causal softmax -> split bf16 probs ---------------
__global__ __launch_bounds__(256) void softmax_causal()
{
    const int row = blockIdx.x;            // h*SEQ + s
    const int s   = row & (SEQ - 1);
    const int len = s + 1;
    const float* p = g_scores + (size_t)row * SEQ;
    bf16* ph = g_p_hi + (size_t)row * SEQ;
    bf16* pl = g_p_lo + (size_t)row * SEQ;
    const int tid = threadIdx.x;

    __shared__ float red[8];

    float m = -1e30f;
    for (int i = tid; i < len; i += 256) m = fmaxf(m, p[i]);
#pragma unroll
    for (int o = 16; o; o >>= 1) m = fmaxf(m, __shfl_xor_sync(0xffffffffu, m, o));
    if ((tid & 31) == 0) red[tid >> 5] = m;
    __syncthreads();
    m = red[0];
#pragma unroll
    for (int i = 1; i < 8; i++) m = fmaxf(m, red[i]);

    float sum = 0.f;
    for (int i = tid; i < len; i += 256) sum += __expf(p[i] - m);
#pragma unroll
    for (int o = 16; o; o >>= 1) sum += __shfl_xor_sync(0xffffffffu, sum, o);
    __syncthreads();
    if ((tid & 31) == 0) red[tid >> 5] = sum;
    __syncthreads();
    sum = 0.f;
#pragma unroll
    for (int i = 0; i < 8; i++) sum += red[i];

    const float inv = 1.0f / sum;
    for (int i = tid; i < len; i += 256) {
        float e = __expf(p[i] - m) * inv;
        bf16 h = __float2bfloat16(e);
        ph[i] = h;
        pl[i] = __float2bfloat16(e - __bfloat162float(h));
    }
    const bf16 z = __float2bfloat16(0.f);
    for (int i = len + tid; i < SEQ; i += 256) { ph[i] = z; pl[i] = z; }
}

// ---------------------------------------------------------------------------
extern "C" void kernel_launch(void* const* d_in, const int* in_sizes, int n_in,
                              void* d_out, int out_size)
{
    const int*   positions = (const int*)d_in[0];
    const float* hidden    = (const float*)d_in[1];
    const float* Wqkv      = (const float*)d_in[2];
    const float* bqkv      = (const float*)d_in[3];
    const float* Wproj     = (const float*)d_in[4];
    const float* bproj     = (const float*)d_in[5];
    float* out = (float*)d_out;

    bf16 *hid_hi, *hid_lo, *wqkv_hi, *wqkv_lo, *wproj_hi, *wproj_lo;
    bf16 *qkv_hi, *qkv_lo, *p_hi, *p_lo, *attn_hi, *attn_lo;
    float *qkv_p, *scores_p, *attn_p;
    cudaGetSymbolAddress((void**)&hid_hi,   g_hid_hi);
    cudaGetSymbolAddress((void**)&hid_lo,   g_hid_lo);
    cudaGetSymbolAddress((void**)&wqkv_hi,  g_wqkv_hi);
    cudaGetSymbolAddress((void**)&wqkv_lo,  g_wqkv_lo);
    cudaGetSymbolAddress((void**)&wproj_hi, g_wproj_hi);
    cudaGetSymbolAddress((void**)&wproj_lo, g_wproj_lo);
    cudaGetSymbolAddress((void**)&qkv_p,    g_qkv);
    cudaGetSymbolAddress((void**)&qkv_hi,   g_qkv_hi);
    cudaGetSymbolAddress((void**)&qkv_lo,   g_qkv_lo);
    cudaGetSymbolAddress((void**)&scores_p, g_scores);
    cudaGetSymbolAddress((void**)&p_hi,     g_p_hi);
    cudaGetSymbolAddress((void**)&p_lo,     g_p_lo);
    cudaGetSymbolAddress((void**)&attn_p,   g_attn);
    cudaGetSymbolAddress((void**)&attn_hi,  g_attn_hi);
    cudaGetSymbolAddress((void**)&attn_lo,  g_attn_lo);

    const float scale = 1.0f / sqrtf((float)HD);

    // 0) split inputs/weights to (hi, lo) bf16
    {
        size_t n1 = (size_t)SEQ * HID;
        split_f32<<<(unsigned)((n1/4 + 255)/256), 256>>>(hidden, hid_hi, hid_lo, n1);
        size_t n2 = (size_t)HID * QKVN;
        split_f32<<<(unsigned)((n2/4 + 255)/256), 256>>>(Wqkv, wqkv_hi, wqkv_lo, n2);
        size_t n3 = (size_t)HID * HID;
        split_f32<<<(unsigned)((n3/4 + 255)/256), 256>>>(Wproj, wproj_hi, wproj_lo, n3);
    }

    // 1) QKV projection: [2048,4096] @ [4096,6144] + bias  (B is K-major -> trans)
    {
        dim3 grid(QKVN / 128, SEQ / 128, 1);
        gemm3<true, false><<<grid, 256>>>(SEQ, QKVN, HID,
            hid_hi, hid_lo, HID, 0,
            wqkv_hi, wqkv_lo, QKVN, 0, 1,
            bqkv, 1.0f, qkv_p, QKVN, 0);
    }

    // 2) RoPE on Q and K (fp32, in place)
    {
        const int total = SEQ * 40 * 64;
        rope_kernel<<<(total + 255) / 256, 256>>>(positions);
    }

    // 3) split post-rope qkv to (hi, lo)
    {
        size_t n = (size_t)SEQ * QKVN;
        split_f32<<<(unsigned)((n/4 + 255)/256), 256>>>(qkv_p, qkv_hi, qkv_lo, n);
    }

    // 4) Scores per head: Q @ K^T * scale  (B is [N=t, K=d] row-major -> no trans)
    {
        dim3 grid(SEQ / 128, SEQ / 128, NQH);
        gemm3<false, true><<<grid, 256>>>(SEQ, SEQ, HD,
            qkv_hi, qkv_lo, QKVN, HD,                 // A: Q head offset = h*128
            qkv_hi + HID, qkv_lo + HID, QKVN, HD, 4,  // B: K head offset = (h/4)*128
            nullptr, scale, scores_p, SEQ, (long long)SEQ * SEQ);
    }

    // 5) causal softmax -> split probs
    softmax_causal<<<NQH * SEQ, 256>>>();

    // 6) P @ V per head  (B is [K=t, N=d] row-major -> trans)
    {
        dim3 grid(1, SEQ / 128, NQH);
        gemm3<true, false><<<grid, 256>>>(SEQ, HD, SEQ,
            p_hi, p_lo, SEQ, (long long)SEQ * SEQ,
            qkv_hi + HID + KVD, qkv_lo + HID + KVD, QKVN, HD, 4,
            nullptr, 1.0f, attn_p, HID, HD);
    }

    // 7) split attn
    {
        size_t n = (size_t)SEQ * HID;
        split_f32<<<(unsigned)((n/4 + 255)/256), 256>>>(attn_p, attn_hi, attn_lo, n);
    }

    // 8) Output projection: [2048,4096] @ [4096,4096] + bias
    {
        dim3 grid(HID / 128, SEQ / 128, 1);
        gemm3<true, false><<<grid, 256>>>(SEQ, HID, HID,
            attn_hi, attn_lo, HID, 0,
            wproj_hi, wproj_lo, HID, 0, 1,
            bproj, 1.0f, out, HID, 0);
    }
}

// round 5
// speedup vs baseline: 2.6734x; 2.6734x over previous
#include <cuda_runtime.h>
#include <cuda_bf16.h>
#include <math.h>

typedef __nv_bfloat16 bf16;

#define SEQ   2048
#define HID   4096
#define NQH   32
#define NKVH  8
#define HD    128
#define KVD   1024
#define QKVN  6144   // 4096 + 2*1024
#define KPAD  40     // padded smem row (bf16 elems): 80B stride, LDSM conflict-free

// ------------------------- device scratch (no allocation allowed) ----------
__device__ __align__(16) bf16 g_hid_hi[(size_t)SEQ * HID];
__device__ __align__(16) bf16 g_hid_lo[(size_t)SEQ * HID];
__device__ __align__(16) bf16 g_wqkvT_hi[(size_t)QKVN * HID];   // [N][K]
__device__ __align__(16) bf16 g_wqkvT_lo[(size_t)QKVN * HID];
__device__ __align__(16) bf16 g_wprojT_hi[(size_t)HID * HID];   // [N][K]
__device__ __align__(16) bf16 g_wprojT_lo[(size_t)HID * HID];
__device__ __align__(16) float g_qkv[(size_t)SEQ * QKVN];
__device__ __align__(16) bf16 g_qkv_hi[(size_t)SEQ * QKVN];
__device__ __align__(16) bf16 g_qkv_lo[(size_t)SEQ * QKVN];
__device__ __align__(16) bf16 g_vt_hi[(size_t)NKVH * HD * SEQ]; // [h][d][t]
__device__ __align__(16) bf16 g_vt_lo[(size_t)NKVH * HD * SEQ];
__device__ __align__(16) float g_scores[(size_t)NQH * SEQ * SEQ];
__device__ __align__(16) bf16 g_p_hi[(size_t)NQH * SEQ * SEQ];
__device__ __align__(16) bf16 g_p_lo[(size_t)NQH * SEQ * SEQ];
__device__ __align__(16) float g_attn[(size_t)SEQ * HID];
__device__ __align__(16) bf16 g_attn_hi[(size_t)SEQ * HID];
__device__ __align__(16) bf16 g_attn_lo[(size_t)SEQ * HID];

// ------------------------- PTX helpers --------------------------------------
__device__ __forceinline__ void mma16816(float* c, const unsigned* a, const unsigned* b)
{
    asm volatile(
        "mma.sync.aligned.m16n8k16.row.col.f32.bf16.bf16.f32 "
        "{%0,%1,%2,%3}, {%4,%5,%6,%7}, {%8,%9}, {%0,%1,%2,%3};\n"
        : "+f"(c[0]), "+f"(c[1]), "+f"(c[2]), "+f"(c[3])
        : "r"(a[0]), "r"(a[1]), "r"(a[2]), "r"(a[3]), "r"(b[0]), "r"(b[1]));
}
__device__ __forceinline__ void ldsm4(unsigned& r0, unsigned& r1, unsigned& r2, unsigned& r3,
                                      unsigned addr)
{
    asm volatile("ldmatrix.sync.aligned.m8n8.x4.shared.b16 {%0,%1,%2,%3}, [%4];\n"
                 : "=r"(r0), "=r"(r1), "=r"(r2), "=r"(r3) : "r"(addr));
}
#define CP16(dst, src) \
    asm volatile("cp.async.cg.shared.global [%0], [%1], 16;\n" :: "r"(dst), "l"(src))
#define CP_COMMIT() asm volatile("cp.async.commit_group;\n")
#define CP_WAIT1()  asm volatile("cp.async.wait_group 1;\n")
#define CP_WAIT0()  asm volatile("cp.async.wait_group 0;\n")

// ------------------------- split fp32 -> (hi, lo) bf16 ----------------------
__global__ void split_f32(const float* __restrict__ in,
                          bf16* __restrict__ hi, bf16* __restrict__ lo, size_t n)
{
    size_t i = ((size_t)blockIdx.x * blockDim.x + threadIdx.x) * 4;
    if (i >= n) return;
    float4 v = *(const float4*)(in + i);
    bf16 h0 = __float2bfloat16(v.x), h1 = __float2bfloat16(v.y);
    bf16 h2 = __float2bfloat16(v.z), h3 = __float2bfloat16(v.w);
    hi[i] = h0; hi[i+1] = h1; hi[i+2] = h2; hi[i+3] = h3;
    lo[i]   = __float2bfloat16(v.x - __bfloat162float(h0));
    lo[i+1] = __float2bfloat16(v.y - __bfloat162float(h1));
    lo[i+2] = __float2bfloat16(v.z - __bfloat162float(h2));
    lo[i+3] = __float2bfloat16(v.w - __bfloat162float(h3));
}

// -------- transposed split: in[k][n] fp32 -> out[n][k] (hi, lo) bf16 --------
__global__ void tsplit_f32(const float* __restrict__ in, int ldin, long long inZ,
                           bf16* __restrict__ hi, bf16* __restrict__ lo,
                           int ldout, long long outZ)
{
    __shared__ float t[32][33];
    const float* I = in + (size_t)blockIdx.z * inZ;
    bf16* H = hi + (size_t)blockIdx.z * outZ;
    bf16* L = lo + (size_t)blockIdx.z * outZ;
    const int k0 = blockIdx.y * 32, n0 = blockIdx.x * 32;
    const int tx = threadIdx.x, ty = threadIdx.y;   // 32 x 8
#pragma unroll
    for (int i = 0; i < 32; i += 8)
        t[ty + i][tx] = I[(size_t)(k0 + ty + i) * ldin + n0 + tx];
    __syncthreads();
#pragma unroll
    for (int i = 0; i < 32; i += 8) {
        float v = t[tx][ty + i];
        bf16 h = __float2bfloat16(v);
        size_t o = (size_t)(n0 + ty + i) * ldout + k0 + tx;
        H[o] = h;
        L[o] = __float2bfloat16(v - __bfloat162float(h));
    }
}

// ---------------------------------------------------------------------------
// One-pass triple-product bf16 GEMM:
//   C = scale*(Ah*Bh + Ah*Bl + Al*Bh) + bias
// A: [M,K] row-major. B: [N,K] row-major ("col" operand). Block 128x128, BK=32.
// 256 threads, 8 warps (2x4), warp tile 64x32. cp.async double-buffer, ldmatrix.
// ---------------------------------------------------------------------------
template<bool CSKIP, bool CK>
__global__ __launch_bounds__(256) void gemm3p(
    int K,
    const bf16* __restrict__ Ahi, const bf16* __restrict__ Alo, int lda, long long sAz,
    const bf16* __restrict__ Bhi, const bf16* __restrict__ Blo, int ldb, long long sBz, int bGroup,
    const float* __restrict__ bias, float scale,
    float* __restrict__ C, int ldc, long long sCz)
{
    const int bx = blockIdx.x, by = blockIdx.y, bz = blockIdx.z;
    if (CSKIP && bx > by) return;   // fully-masked causal tile

    extern __shared__ bf16 smem[];  // 2 stages x 4 tiles x 128 x KPAD
    const unsigned smemBase = (unsigned)__cvta_generic_to_shared(smem);
    // per-stage byte offsets: Ah 0, Al 10240, Bh 20480, Bl 30720; stage stride 40960

    const bf16* Ah = Ahi + (size_t)bz * sAz;
    const bf16* Al = Alo + (size_t)bz * sAz;
    const bf16* Bh = Bhi + (size_t)(bz / bGroup) * sBz;
    const bf16* Bl = Blo + (size_t)(bz / bGroup) * sBz;
    float* Cb = C + (size_t)bz * sCz + (size_t)by * 128 * ldc + (size_t)bx * 128;

    const int tid  = threadIdx.x;
    const int warp = tid >> 5, lane = tid & 31;
    const int wm = warp >> 2, wn = warp & 3;       // 2 x 4 warp grid
    const int g = lane >> 2, t4 = lane & 3;

    // cp.async mapping: row0 = tid>>2 (0..63), row1 = row0+64, chunk = tid&3
    const int r0 = tid >> 2, r1 = r0 + 64;
    const int ch = tid & 3;                        // 16B chunk -> col = ch*8 elems

    const int nk = (CK ? (by + 1) * 128 : K) >> 5;

    auto loadStage = [&](int s, int kt) {
        const int k0 = kt * 32 + ch * 8;
        const unsigned sb = smemBase + s * 40960;
        const unsigned d0 = sb + r0 * (KPAD * 2) + ch * 16;
        const unsigned d1 = sb + r1 * (KPAD * 2) + ch * 16;
        const bf16* a0 = Ah + (size_t)(by * 128 + r0) * lda + k0;
        const bf16* a1 = Ah + (size_t)(by * 128 + r1) * lda + k0;
        const bf16* c0 = Al + (size_t)(by * 128 + r0) * lda + k0;
        const bf16* c1 = Al + (size_t)(by * 128 + r1) * lda + k0;
        const bf16* b0 = Bh + (size_t)(bx * 128 + r0) * ldb + k0;
        const bf16* b1 = Bh + (size_t)(bx * 128 + r1) * ldb + k0;
        const bf16* e0 = Bl + (size_t)(bx * 128 + r0) * ldb + k0;
        const bf16* e1 = Bl + (size_t)(bx * 128 + r1) * ldb + k0;
        CP16(d0,         a0); CP16(d1,         a1);
        CP16(d0 + 10240, c0); CP16(d1 + 10240, c1);
        CP16(d0 + 20480, b0); CP16(d1 + 20480, b1);
        CP16(d0 + 30720, e0); CP16(d1 + 30720, e1);
    };

    float acc[4][4][4];
#pragma unroll
    for (int i = 0; i < 4; i++)
#pragma unroll
        for (int j = 0; j < 4; j++)
#pragma unroll
            for (int q = 0; q < 4; q++) acc[i][j][q] = 0.f;

    loadStage(0, 0);
    CP_COMMIT();

    const int arow = lane & 15;          // ldmatrix row within 16
    const int csel = (lane >> 4) << 3;   // +8 elems for mats 2,3

    for (int kt = 0; kt < nk; kt++) {
        const int cur = kt & 1;
        if (kt + 1 < nk) { loadStage(cur ^ 1, kt + 1); CP_COMMIT(); CP_WAIT1(); }
        else            { CP_WAIT0(); }
        __syncthreads();

        const unsigned sb = smemBase + cur * 40960;
#pragma unroll
        for (int ks = 0; ks < 2; ks++) {
            const int c0 = ks * 16 + csel;
            unsigned A_[4][4], AL_[4][4], BH_[4][2], BL_[4][2];
#pragma unroll
            for (int mt = 0; mt < 4; mt++) {
                const unsigned ad = sb + ((wm * 64 + mt * 16 + arow) * KPAD + c0) * 2;
                ldsm4(A_[mt][0], A_[mt][1], A_[mt][2], A_[mt][3], ad);
            }
#pragma unroll
            for (int p = 0; p < 2; p++) {
                unsigned q0, q1, q2, q3;
                const unsigned bd = sb + 20480 + ((wn * 32 + p * 16 + arow) * KPAD + c0) * 2;
                ldsm4(q0, q1, q2, q3, bd);
                BH_[2 * p][0] = q0; BH_[2 * p][1] = q2;
                BH_[2 * p + 1][0] = q1; BH_[2 * p + 1][1] = q3;
                const unsigned ed = bd + 10240;
                ldsm4(q0, q1, q2, q3, ed);
                BL_[2 * p][0] = q0; BL_[2 * p][1] = q2;
                BL_[2 * p + 1][0] = q1; BL_[2 * p + 1][1] = q3;
            }
#pragma unroll
            for (int mt = 0; mt < 4; mt++)
#pragma unroll
                for (int nt = 0; nt < 4; nt++)
                    mma16816(acc[mt][nt], A_[mt], BH_[nt]);
#pragma unroll
            for (int mt = 0; mt < 4; mt++)
#pragma unroll
                for (int nt = 0; nt < 4; nt++)
                    mma16816(acc[mt][nt], A_[mt], BL_[nt]);
#pragma unroll
            for (int mt = 0; mt < 4; mt++) {
                const unsigned ad = sb + 10240 + ((wm * 64 + mt * 16 + arow) * KPAD + c0) * 2;
                ldsm4(AL_[mt][0], AL_[mt][1], AL_[mt][2], AL_[mt][3], ad);
            }
#pragma unroll
            for (int mt = 0; mt < 4; mt++)
#pragma unroll
                for (int nt = 0; nt < 4; nt++)
                    mma16816(acc[mt][nt], AL_[mt], BH_[nt]);
        }
        __syncthreads();
    }

    // epilogue
#pragma unroll
    for (int mt = 0; mt < 4; mt++) {
        const int r = wm * 64 + mt * 16 + g;
#pragma unroll
        for (int nt = 0; nt < 4; nt++) {
            const int cl = wn * 32 + nt * 8 + 2 * t4;
            float b0 = 0.f, b1 = 0.f;
            if (bias) {
                const int gcol = bx * 128 + cl;
                b0 = bias[gcol]; b1 = bias[gcol + 1];
            }
            float2 v0 = make_float2(acc[mt][nt][0] * scale + b0,
                                    acc[mt][nt][1] * scale + b1);
            float2 v1 = make_float2(acc[mt][nt][2] * scale + b0,
                                    acc[mt][nt][3] * scale + b1);
            *(float2*)(Cb + (size_t)r * ldc + cl) = v0;
            *(float2*)(Cb + (size_t)(r + 8) * ldc + cl) = v1;
        }
    }
}

// ------------------------- RoPE (in-place, fp32 qkv) ------------------------
__global__ void rope_kernel(const int* __restrict__ positions)
{
    const int total = SEQ * 40 * 64;
    int idx = blockIdx.x * blockDim.x + threadIdx.x;
    if (idx >= total) return;
    const int i    = idx & 63;
    const int head = (idx >> 6) % 40;   // 0..31 Q, 32..39 K
    const int s    = idx / (40 * 64);

    float* base = g_qkv + (size_t)s * QKVN +
                  (head < 32 ? head * HD : HID + (head - 32) * HD);

    const double pos = (double)positions[s];
    const double inv_freq = exp(-(double)i * (9.210340371976184 / 64.0));
    const double a = pos * inv_freq;
    const float c  = (float)cos(a);
    const float sn = (float)sin(a);

    const float x1 = base[i];
    const float x2 = base[i + 64];
    base[i]      = x1 * c - x2 * sn;
    base[i + 64] = x2 * c + x1 * sn;
}

// ------------------------- causal softmax -> split bf16 probs ---------------
__global__ __launch_bounds__(256) void softmax_causal()
{
    const int row = blockIdx.x;            // h*SEQ + s
    const int s   = row & (SEQ - 1);
    const int len = s + 1;
    const float* p = g_scores + (size_t)row * SEQ;
    bf16* ph = g_p_hi + (size_t)row * SEQ;
    bf16* pl = g_p_lo + (size_t)row * SEQ;
    const int tid = threadIdx.x;

    __shared__ float red[8];

    float m = -1e30f;
    for (int i = tid; i < len; i += 256) m = fmaxf(m, p[i]);
#pragma unroll
    for (int o = 16; o; o >>= 1) m = fmaxf(m, __shfl_xor_sync(0xffffffffu, m, o));
    if ((tid & 31) == 0) red[tid >> 5] = m;
    __syncthreads();
    m = red[0];
#pragma unroll
    for (int i = 1; i < 8; i++) m = fmaxf(m, red[i]);

    float sum = 0.f;
    for (int i = tid; i < len; i += 256) sum += __expf(p[i] - m);
#pragma unroll
    for (int o = 16; o; o >>= 1) sum += __shfl_xor_sync(0xffffffffu, sum, o);
    __syncthreads();
    if ((tid & 31) == 0) red[tid >> 5] = sum;
    __syncthreads();
    sum = 0.f;
#pragma unroll
    for (int i = 0; i < 8; i++) sum += red[i];

    const float inv = 1.0f / sum;
    for (int i = tid; i < len; i += 256) {
        float e = __expf(p[i] - m) * inv;
        bf16 h = __float2bfloat16(e);
        ph[i] = h;
        pl[i] = __float2bfloat16(e - __bfloat162float(h));
    }
    const bf16 z = __float2bfloat16(0.f);
    for (int i = len + tid; i < SEQ; i += 256) { ph[i] = z; pl[i] = z; }
}

// ---------------------------------------------------------------------------
extern "C" void kernel_launch(void* const* d_in, const int* in_sizes, int n_in,
                              void* d_out, int out_size)
{
    const int*   positions = (const int*)d_in[0];
    const float* hidden    = (const float*)d_in[1];
    const float* Wqkv      = (const float*)d_in[2];
    const float* bqkv      = (const float*)d_in[3];
    const float* Wproj     = (const float*)d_in[4];
    const float* bproj     = (const float*)d_in[5];
    float* out = (float*)d_out;

    bf16 *hid_hi, *hid_lo, *wqkvT_hi, *wqkvT_lo, *wprojT_hi, *wprojT_lo;
    bf16 *qkv_hi, *qkv_lo, *vt_hi, *vt_lo, *p_hi, *p_lo, *attn_hi, *attn_lo;
    float *qkv_p, *scores_p, *attn_p;
    cudaGetSymbolAddress((void**)&hid_hi,    g_hid_hi);
    cudaGetSymbolAddress((void**)&hid_lo,    g_hid_lo);
    cudaGetSymbolAddress((void**)&wqkvT_hi,  g_wqkvT_hi);
    cudaGetSymbolAddress((void**)&wqkvT_lo,  g_wqkvT_lo);
    cudaGetSymbolAddress((void**)&wprojT_hi, g_wprojT_hi);
    cudaGetSymbolAddress((void**)&wprojT_lo, g_wprojT_lo);
    cudaGetSymbolAddress((void**)&qkv_p,     g_qkv);
    cudaGetSymbolAddress((void**)&qkv_hi,    g_qkv_hi);
    cudaGetSymbolAddress((void**)&qkv_lo,    g_qkv_lo);
    cudaGetSymbolAddress((void**)&vt_hi,     g_vt_hi);
    cudaGetSymbolAddress((void**)&vt_lo,     g_vt_lo);
    cudaGetSymbolAddress((void**)&scores_p,  g_scores);
    cudaGetSymbolAddress((void**)&p_hi,      g_p_hi);
    cudaGetSymbolAddress((void**)&p_lo,      g_p_lo);
    cudaGetSymbolAddress((void**)&attn_p,    g_attn);
    cudaGetSymbolAddress((void**)&attn_hi,   g_attn_hi);
    cudaGetSymbolAddress((void**)&attn_lo,   g_attn_lo);

    const int SMEM_BYTES = 2 * 4 * 128 * KPAD * 2;   // 81920
    cudaFuncSetAttribute(gemm3p<false, false>, cudaFuncAttributeMaxDynamicSharedMemorySize, SMEM_BYTES);
    cudaFuncSetAttribute(gemm3p<true,  false>, cudaFuncAttributeMaxDynamicSharedMemorySize, SMEM_BYTES);
    cudaFuncSetAttribute(gemm3p<false, true >, cudaFuncAttributeMaxDynamicSharedMemorySize, SMEM_BYTES);

    const float scale = 1.0f / sqrtf((float)HD);

    // 0) splits: hidden (plain), Wqkv/Wproj (transposed)
    {
        size_t n1 = (size_t)SEQ * HID;
        split_f32<<<(unsigned)((n1/4 + 255)/256), 256>>>(hidden, hid_hi, hid_lo, n1);
        dim3 tb(32, 8);
        tsplit_f32<<<dim3(QKVN/32, HID/32, 1), tb>>>(Wqkv, QKVN, 0, wqkvT_hi, wqkvT_lo, HID, 0);
        tsplit_f32<<<dim3(HID/32, HID/32, 1),  tb>>>(Wproj, HID, 0, wprojT_hi, wprojT_lo, HID, 0);
    }

    // 1) QKV projection: [2048,4096] @ [4096,6144] + bias
    gemm3p<false, false><<<dim3(QKVN/128, SEQ/128, 1), 256, SMEM_BYTES>>>(
        HID, hid_hi, hid_lo, HID, 0,
        wqkvT_hi, wqkvT_lo, HID, 0, 1,
        bqkv, 1.0f, qkv_p, QKVN, 0);

    // 2) RoPE on Q and K
    rope_kernel<<<(SEQ * 40 * 64 + 255) / 256, 256>>>(positions);

    // 3) split qkv; transpose-split V per KV head
    {
        size_t n = (size_t)SEQ * QKVN;
        split_f32<<<(unsigned)((n/4 + 255)/256), 256>>>(qkv_p, qkv_hi, qkv_lo, n);
        dim3 tb(32, 8);
        tsplit_f32<<<dim3(HD/32, SEQ/32, NKVH), tb>>>(
            qkv_p + HID + KVD, QKVN, HD, vt_hi, vt_lo, SEQ, (long long)HD * SEQ);
    }

    // 4) Scores per head: Q @ K^T * scale (K rows ARE [t][d] row-major already)
    gemm3p<true, false><<<dim3(SEQ/128, SEQ/128, NQH), 256, SMEM_BYTES>>>(
        HD, qkv_hi, qkv_lo, QKVN, HD,
        qkv_hi + HID, qkv_lo + HID, QKVN, HD, 4,
        nullptr, scale, scores_p, SEQ, (long long)SEQ * SEQ);

    // 5) causal softmax -> split probs
    softmax_causal<<<NQH * SEQ, 256>>>();

    // 6) P @ V per head (B = V^T pre-transposed, causal K-limit)
    gemm3p<false, true><<<dim3(1, SEQ/128, NQH), 256, SMEM_BYTES>>>(
        SEQ, p_hi, p_lo, SEQ, (long long)SEQ * SEQ,
        vt_hi, vt_lo, SEQ, (long long)HD * SEQ, 4,
        nullptr, 1.0f, attn_p, HID, HD);

    // 7) split attn
    {
        size_t n = (size_t)SEQ * HID;
        split_f32<<<(unsigned)((n/4 + 255)/256), 256>>>(attn_p, attn_hi, attn_lo, n);
    }

    // 8) Output projection: [2048,4096] @ [4096,4096] + bias
    gemm3p<false, false><<<dim3(HID/128, SEQ/128, 1), 256, SMEM_BYTES>>>(
        HID, attn_hi, attn_lo, HID, 0,
        wprojT_hi, wprojT_lo, HID, 0, 1,
        bproj, 1.0f, out, HID, 0);
}

// round 6
// speedup vs baseline: 4.4207x; 1.6536x over previous
#include <cuda_runtime.h>
#include <cuda_bf16.h>
#include <math.h>

typedef __nv_bfloat16 bf16;

#define SEQ   2048
#define HID   4096
#define NQH   32
#define NKVH  8
#define HD    128
#define KVD   1024
#define QKVN  6144   // 4096 + 2*1024
#define KPAD  40     // gemm smem row pad (bf16 elems)

// ------------------------- device scratch (no allocation allowed) ----------
__device__ __align__(16) bf16 g_hid_hi[(size_t)SEQ * HID];
__device__ __align__(16) bf16 g_hid_lo[(size_t)SEQ * HID];
__device__ __align__(16) bf16 g_wqkvT_hi[(size_t)QKVN * HID];   // [N][K]
__device__ __align__(16) bf16 g_wqkvT_lo[(size_t)QKVN * HID];
__device__ __align__(16) bf16 g_wprojT_hi[(size_t)HID * HID];   // [N][K]
__device__ __align__(16) bf16 g_wprojT_lo[(size_t)HID * HID];
__device__ __align__(16) float g_qkv[(size_t)SEQ * QKVN];
__device__ __align__(16) bf16 g_qkv_hi[(size_t)SEQ * QKVN];
__device__ __align__(16) bf16 g_qkv_lo[(size_t)SEQ * QKVN];
__device__ __align__(16) bf16 g_vt_hi[(size_t)NKVH * HD * SEQ]; // [h][d][t]
__device__ __align__(16) bf16 g_vt_lo[(size_t)NKVH * HD * SEQ];
__device__ __align__(16) bf16 g_attn_hi[(size_t)SEQ * HID];
__device__ __align__(16) bf16 g_attn_lo[(size_t)SEQ * HID];

// ------------------------- PTX helpers --------------------------------------
__device__ __forceinline__ void mma16816(float* c, const unsigned* a, const unsigned* b)
{
    asm volatile(
        "mma.sync.aligned.m16n8k16.row.col.f32.bf16.bf16.f32 "
        "{%0,%1,%2,%3}, {%4,%5,%6,%7}, {%8,%9}, {%0,%1,%2,%3};\n"
        : "+f"(c[0]), "+f"(c[1]), "+f"(c[2]), "+f"(c[3])
        : "r"(a[0]), "r"(a[1]), "r"(a[2]), "r"(a[3]), "r"(b[0]), "r"(b[1]));
}
__device__ __forceinline__ void ldsm4(unsigned& r0, unsigned& r1, unsigned& r2, unsigned& r3,
                                      unsigned addr)
{
    asm volatile("ldmatrix.sync.aligned.m8n8.x4.shared.b16 {%0,%1,%2,%3}, [%4];\n"
                 : "=r"(r0), "=r"(r1), "=r"(r2), "=r"(r3) : "r"(addr));
}
#define CP16(dst, src) \
    asm volatile("cp.async.cg.shared.global [%0], [%1], 16;\n" :: "r"(dst), "l"(src))
#define CP_COMMIT() asm volatile("cp.async.commit_group;\n")
#define CP_WAIT1()  asm volatile("cp.async.wait_group 1;\n")
#define CP_WAIT0()  asm volatile("cp.async.wait_group 0;\n")

__device__ __forceinline__ void pack_hl(float a, float b, unsigned& h, unsigned& l)
{
    bf16 ha = __float2bfloat16(a), hb = __float2bfloat16(b);
    __nv_bfloat162 hh; hh.x = ha; hh.y = hb;
    h = *(unsigned*)&hh;
    bf16 la = __float2bfloat16(a - __bfloat162float(ha));
    bf16 lb = __float2bfloat16(b - __bfloat162float(hb));
    __nv_bfloat162 ll; ll.x = la; ll.y = lb;
    l = *(unsigned*)&ll;
}

// ------------------------- split fp32 -> (hi, lo) bf16 ----------------------
__global__ void split_f32(const float* __restrict__ in,
                          bf16* __restrict__ hi, bf16* __restrict__ lo, size_t n)
{
    size_t i = ((size_t)blockIdx.x * blockDim.x + threadIdx.x) * 4;
    if (i >= n) return;
    float4 v = *(const float4*)(in + i);
    bf16 h0 = __float2bfloat16(v.x), h1 = __float2bfloat16(v.y);
    bf16 h2 = __float2bfloat16(v.z), h3 = __float2bfloat16(v.w);
    hi[i] = h0; hi[i+1] = h1; hi[i+2] = h2; hi[i+3] = h3;
    lo[i]   = __float2bfloat16(v.x - __bfloat162float(h0));
    lo[i+1] = __float2bfloat16(v.y - __bfloat162float(h1));
    lo[i+2] = __float2bfloat16(v.z - __bfloat162float(h2));
    lo[i+3] = __float2bfloat16(v.w - __bfloat162float(h3));
}

// -------- transposed split: in[k][n] fp32 -> out[n][k] (hi, lo) bf16 --------
__global__ void tsplit_f32(const float* __restrict__ in, int ldin, long long inZ,
                           bf16* __restrict__ hi, bf16* __restrict__ lo,
                           int ldout, long long outZ)
{
    __shared__ float t[32][33];
    const float* I = in + (size_t)blockIdx.z * inZ;
    bf16* H = hi + (size_t)blockIdx.z * outZ;
    bf16* L = lo + (size_t)blockIdx.z * outZ;
    const int k0 = blockIdx.y * 32, n0 = blockIdx.x * 32;
    const int tx = threadIdx.x, ty = threadIdx.y;   // 32 x 8
#pragma unroll
    for (int i = 0; i < 32; i += 8)
        t[ty + i][tx] = I[(size_t)(k0 + ty + i) * ldin + n0 + tx];
    __syncthreads();
#pragma unroll
    for (int i = 0; i < 32; i += 8) {
        float v = t[tx][ty + i];
        bf16 h = __float2bfloat16(v);
        size_t o = (size_t)(n0 + ty + i) * ldout + k0 + tx;
        H[o] = h;
        L[o] = __float2bfloat16(v - __bfloat162float(h));
    }
}

// ---------------------------------------------------------------------------
// One-pass triple-product bf16 GEMM (dense projections):
//   C = scale*(Ah*Bh + Ah*Bl + Al*Bh) + bias
// A: [M,K] row-major. B: [N,K] row-major. 128x128 block, BK=32, 256 threads.
// ---------------------------------------------------------------------------
__global__ __launch_bounds__(256, 2) void gemm3p(
    int K,
    const bf16* __restrict__ Ahi, const bf16* __restrict__ Alo, int lda,
    const bf16* __restrict__ Bhi, const bf16* __restrict__ Blo, int ldb,
    const float* __restrict__ bias, float scale,
    float* __restrict__ C, int ldc)
{
    const int bx = blockIdx.x, by = blockIdx.y;

    extern __shared__ bf16 smem[];  // 2 stages x 4 tiles x 128 x KPAD
    const unsigned smemBase = (unsigned)__cvta_generic_to_shared(smem);

    float* Cb = C + (size_t)by * 128 * ldc + (size_t)bx * 128;

    const int tid  = threadIdx.x;
    const int warp = tid >> 5, lane = tid & 31;
    const int wm = warp >> 2, wn = warp & 3;
    const int g = lane >> 2, t4 = lane & 3;

    const int r0 = tid >> 2, r1 = r0 + 64;
    const int ch = tid & 3;

    const int nk = K >> 5;

    auto loadStage = [&](int s, int kt) {
        const int k0 = kt * 32 + ch * 8;
        const unsigned sb = smemBase + s * 40960;
        const unsigned d0 = sb + r0 * (KPAD * 2) + ch * 16;
        const unsigned d1 = sb + r1 * (KPAD * 2) + ch * 16;
        CP16(d0,         Ahi + (size_t)(by * 128 + r0) * lda + k0);
        CP16(d1,         Ahi + (size_t)(by * 128 + r1) * lda + k0);
        CP16(d0 + 10240, Alo + (size_t)(by * 128 + r0) * lda + k0);
        CP16(d1 + 10240, Alo + (size_t)(by * 128 + r1) * lda + k0);
        CP16(d0 + 20480, Bhi + (size_t)(bx * 128 + r0) * ldb + k0);
        CP16(d1 + 20480, Bhi + (size_t)(bx * 128 + r1) * ldb + k0);
        CP16(d0 + 30720, Blo + (size_t)(bx * 128 + r0) * ldb + k0);
        CP16(d1 + 30720, Blo + (size_t)(bx * 128 + r1) * ldb + k0);
    };

    float acc[4][4][4];
#pragma unroll
    for (int i = 0; i < 4; i++)
#pragma unroll
        for (int j = 0; j < 4; j++)
#pragma unroll
            for (int q = 0; q < 4; q++) acc[i][j][q] = 0.f;

    loadStage(0, 0);
    CP_COMMIT();

    const int arow = lane & 15;
    const int csel = (lane >> 4) << 3;

    for (int kt = 0; kt < nk; kt++) {
        const int cur = kt & 1;
        if (kt + 1 < nk) { loadStage(cur ^ 1, kt + 1); CP_COMMIT(); CP_WAIT1(); }
        else            { CP_WAIT0(); }
        __syncthreads();

        const unsigned sb = smemBase + cur * 40960;
#pragma unroll
        for (int ks = 0; ks < 2; ks++) {
            const int c0 = ks * 16 + csel;
            unsigned A_[4][4], AL_[4][4], BH_[4][2], BL_[4][2];
#pragma unroll
            for (int mt = 0; mt < 4; mt++) {
                const unsigned ad = sb + ((wm * 64 + mt * 16 + arow) * KPAD + c0) * 2;
                ldsm4(A_[mt][0], A_[mt][1], A_[mt][2], A_[mt][3], ad);
            }
#pragma unroll
            for (int p = 0; p < 2; p++) {
                unsigned q0, q1, q2, q3;
                const unsigned bd = sb + 20480 + ((wn * 32 + p * 16 + arow) * KPAD + c0) * 2;
                ldsm4(q0, q1, q2, q3, bd);
                BH_[2 * p][0] = q0; BH_[2 * p][1] = q2;
                BH_[2 * p + 1][0] = q1; BH_[2 * p + 1][1] = q3;
                ldsm4(q0, q1, q2, q3, bd + 10240);
                BL_[2 * p][0] = q0; BL_[2 * p][1] = q2;
                BL_[2 * p + 1][0] = q1; BL_[2 * p + 1][1] = q3;
            }
#pragma unroll
            for (int mt = 0; mt < 4; mt++)
#pragma unroll
                for (int nt = 0; nt < 4; nt++)
                    mma16816(acc[mt][nt], A_[mt], BH_[nt]);
#pragma unroll
            for (int mt = 0; mt < 4; mt++)
#pragma unroll
                for (int nt = 0; nt < 4; nt++)
                    mma16816(acc[mt][nt], A_[mt], BL_[nt]);
#pragma unroll
            for (int mt = 0; mt < 4; mt++) {
                const unsigned ad = sb + 10240 + ((wm * 64 + mt * 16 + arow) * KPAD + c0) * 2;
                ldsm4(AL_[mt][0], AL_[mt][1], AL_[mt][2], AL_[mt][3], ad);
            }
#pragma unroll
            for (int mt = 0; mt < 4; mt++)
#pragma unroll
                for (int nt = 0; nt < 4; nt++)
                    mma16816(acc[mt][nt], AL_[mt], BH_[nt]);
        }
        __syncthreads();
    }

#pragma unroll
    for (int mt = 0; mt < 4; mt++) {
        const int r = wm * 64 + mt * 16 + g;
#pragma unroll
        for (int nt = 0; nt < 4; nt++) {
            const int cl = wn * 32 + nt * 8 + 2 * t4;
            float b0 = 0.f, b1 = 0.f;
            if (bias) {
                const int gcol = bx * 128 + cl;
                b0 = bias[gcol]; b1 = bias[gcol + 1];
            }
            float2 v0 = make_float2(acc[mt][nt][0] * scale + b0,
                                    acc[mt][nt][1] * scale + b1);
            float2 v1 = make_float2(acc[mt][nt][2] * scale + b0,
                                    acc[mt][nt][3] * scale + b1);
            *(float2*)(Cb + (size_t)r * ldc + cl) = v0;
            *(float2*)(Cb + (size_t)(r + 8) * ldc + cl) = v1;
        }
    }
}

// ---------------------------------------------------------------------------
// Fused flash attention (split-precision bf16 mma, causal).
// CTA: 128 Q rows x 1 head. 8 warps, warp = 16 rows. KV blocks of 64.
// smem: Q hi/lo resident (128x136), K(64x136)+V^T(128x72) hi/lo double-buffered.
// ---------------------------------------------------------------------------
#define OFF_QL   34816
#define OFF_KV   69632
#define STAGE_B  71680
#define OFF_KL   17408
#define OFF_VH   34816
#define OFF_VL   53248
#define SMEM_FLASH (OFF_KV + 2 * STAGE_B)   // 212992

__global__ __launch_bounds__(256) void flash_attn(float kl2)
{
    const int h  = blockIdx.y;
    const int by = 15 - blockIdx.x;        // heavy tiles first
    const int rowbase = by * 128;
    const int jmax = 2 * by + 1;
    const int hk = h >> 2;

    extern __shared__ bf16 smem[];
    const unsigned SB = (unsigned)__cvta_generic_to_shared(smem);

    const bf16* Qh = g_qkv_hi;
    const bf16* Ql = g_qkv_lo;
    const bf16* Kh = g_qkv_hi + HID;
    const bf16* Kl = g_qkv_lo + HID;
    const bf16* Vh = g_vt_hi + (size_t)hk * HD * SEQ;
    const bf16* Vl = g_vt_lo + (size_t)hk * HD * SEQ;

    const int tid  = threadIdx.x;
    const int w    = tid >> 5, lane = tid & 31;
    const int g    = lane >> 2, t4 = lane & 3;
    const int arow = lane & 15, csel = (lane >> 4) << 3;

    // ---- Q tile (hi+lo) -> smem
    for (int c = tid; c < 2048; c += 256) {
        const int row = c >> 4, cc = c & 15;
        const unsigned dq = SB + row * 272 + cc * 16;
        const size_t go = (size_t)(rowbase + row) * QKVN + h * HD + cc * 8;
        CP16(dq,              Qh + go);
        CP16(dq + OFF_QL * 1, Ql + go);
    }

    auto loadKV = [&](int st, int j) {
        const unsigned sb = SB + OFF_KV + st * STAGE_B;
        for (int c = tid; c < 1024; c += 256) {
            const int row = c >> 4, cc = c & 15;
            const unsigned d = sb + row * 272 + cc * 16;
            const size_t go = (size_t)(j * 64 + row) * QKVN + hk * HD + cc * 8;
            CP16(d,          Kh + go);
            CP16(d + OFF_KL, Kl + go);
        }
        for (int c = tid; c < 1024; c += 256) {
            const int row = c >> 3, cc = c & 7;
            const unsigned d = sb + OFF_VH + row * 144 + cc * 16;
            const size_t go = (size_t)row * SEQ + j * 64 + cc * 8;
            CP16(d,                     Vh + go);
            CP16(d + (OFF_VL - OFF_VH), Vl + go);
        }
    };

    loadKV(0, 0);
    CP_COMMIT();

    float O[16][4];
#pragma unroll
    for (int i = 0; i < 16; i++)
#pragma unroll
        for (int q = 0; q < 4; q++) O[i][q] = 0.f;
    float m0 = -1e30f, m1 = -1e30f, l0 = 0.f, l1 = 0.f;

    const int r0g = rowbase + w * 16 + g;

    for (int j = 0; j <= jmax; j++) {
        const int cur = j & 1;
        if (j < jmax) { loadKV(cur ^ 1, j + 1); CP_COMMIT(); CP_WAIT1(); }
        else          { CP_WAIT0(); }
        __syncthreads();

        const unsigned kb = SB + OFF_KV + cur * STAGE_B;

        // ---- S = Q K^T (triple product), warp rows w*16..+15, cols 64
        float S[8][4];
#pragma unroll
        for (int i = 0; i < 8; i++)
#pragma unroll
            for (int q = 0; q < 4; q++) S[i][q] = 0.f;

#pragma unroll
        for (int ks = 0; ks < 8; ks++) {
            const int c0 = ks * 16 + csel;
            unsigned ah[4], al[4], BH_[8][2], BL_[8][2];
            const unsigned qa = SB + (w * 16 + arow) * 272 + c0 * 2;
            ldsm4(ah[0], ah[1], ah[2], ah[3], qa);
            ldsm4(al[0], al[1], al[2], al[3], qa + OFF_QL);
#pragma unroll
            for (int p = 0; p < 4; p++) {
                unsigned q0, q1, q2, q3;
                const unsigned ka = kb + (p * 16 + arow) * 272 + c0 * 2;
                ldsm4(q0, q1, q2, q3, ka);
                BH_[2 * p][0] = q0; BH_[2 * p][1] = q2;
                BH_[2 * p + 1][0] = q1; BH_[2 * p + 1][1] = q3;
                ldsm4(q0, q1, q2, q3, ka + OFF_KL);
                BL_[2 * p][0] = q0; BL_[2 * p][1] = q2;
                BL_[2 * p + 1][0] = q1; BL_[2 * p + 1][1] = q3;
            }
#pragma unroll
            for (int nt = 0; nt < 8; nt++) {
                mma16816(S[nt], ah, BH_[nt]);
                mma16816(S[nt], ah, BL_[nt]);
                mma16816(S[nt], al, BH_[nt]);
            }
        }

        // ---- causal mask (only diagonal blocks)
        if (j >= 2 * by) {
#pragma unroll
            for (int nt = 0; nt < 8; nt++) {
                const int colb = j * 64 + nt * 8 + 2 * t4;
                if (colb     > r0g)     S[nt][0] = -1e30f;
                if (colb + 1 > r0g)     S[nt][1] = -1e30f;
                if (colb     > r0g + 8) S[nt][2] = -1e30f;
                if (colb + 1 > r0g + 8) S[nt][3] = -1e30f;
            }
        }

        // ---- online softmax
        float mx0 = -1e30f, mx1 = -1e30f;
#pragma unroll
        for (int nt = 0; nt < 8; nt++) {
            mx0 = fmaxf(mx0, fmaxf(S[nt][0], S[nt][1]));
            mx1 = fmaxf(mx1, fmaxf(S[nt][2], S[nt][3]));
        }
        mx0 = fmaxf(mx0, __shfl_xor_sync(0xffffffffu, mx0, 1));
        mx0 = fmaxf(mx0, __shfl_xor_sync(0xffffffffu, mx0, 2));
        mx1 = fmaxf(mx1, __shfl_xor_sync(0xffffffffu, mx1, 1));
        mx1 = fmaxf(mx1, __shfl_xor_sync(0xffffffffu, mx1, 2));
        const float mn0 = fmaxf(m0, mx0), mn1 = fmaxf(m1, mx1);
        const float f0 = exp2f((m0 - mn0) * kl2);
        const float f1 = exp2f((m1 - mn1) * kl2);
        m0 = mn0; m1 = mn1;

        float s0 = 0.f, s1 = 0.f;
#pragma unroll
        for (int nt = 0; nt < 8; nt++) {
            S[nt][0] = exp2f((S[nt][0] - m0) * kl2);
            S[nt][1] = exp2f((S[nt][1] - m0) * kl2);
            S[nt][2] = exp2f((S[nt][2] - m1) * kl2);
            S[nt][3] = exp2f((S[nt][3] - m1) * kl2);
            s0 += S[nt][0] + S[nt][1];
            s1 += S[nt][2] + S[nt][3];
        }
        s0 += __shfl_xor_sync(0xffffffffu, s0, 1);
        s0 += __shfl_xor_sync(0xffffffffu, s0, 2);
        s1 += __shfl_xor_sync(0xffffffffu, s1, 1);
        s1 += __shfl_xor_sync(0xffffffffu, s1, 2);
        l0 = l0 * f0 + s0;
        l1 = l1 * f1 + s1;
#pragma unroll
        for (int i = 0; i < 16; i++) {
            O[i][0] *= f0; O[i][1] *= f0;
            O[i][2] *= f1; O[i][3] *= f1;
        }

        // ---- pack P -> hi/lo A-fragments (in registers)
        unsigned Ph[4][4], Pl[4][4];
#pragma unroll
        for (int kt = 0; kt < 4; kt++) {
            pack_hl(S[2 * kt][0],     S[2 * kt][1],     Ph[kt][0], Pl[kt][0]);
            pack_hl(S[2 * kt][2],     S[2 * kt][3],     Ph[kt][1], Pl[kt][1]);
            pack_hl(S[2 * kt + 1][0], S[2 * kt + 1][1], Ph[kt][2], Pl[kt][2]);
            pack_hl(S[2 * kt + 1][2], S[2 * kt + 1][3], Ph[kt][3], Pl[kt][3]);
        }

        // ---- O += P V (triple product). V^T rows = d (128), cols = t (64)
#pragma unroll
        for (int p = 0; p < 8; p++) {
#pragma unroll
            for (int ks = 0; ks < 4; ks++) {
                unsigned v0, v1, v2, v3, u0, u1, u2, u3;
                const unsigned va = kb + OFF_VH + (p * 16 + arow) * 144 + (ks * 16 + csel) * 2;
                ldsm4(v0, v1, v2, v3, va);
                ldsm4(u0, u1, u2, u3, va + (OFF_VL - OFF_VH));
                unsigned bh0[2] = {v0, v2}, bh1[2] = {v1, v3};
                unsigned bl0[2] = {u0, u2}, bl1[2] = {u1, u3};
                mma16816(O[2 * p],     Ph[ks], bh0);
                mma16816(O[2 * p],     Ph[ks], bl0);
                mma16816(O[2 * p],     Pl[ks], bh0);
                mma16816(O[2 * p + 1], Ph[ks], bh1);
                mma16816(O[2 * p + 1], Ph[ks], bl1);
                mma16816(O[2 * p + 1], Pl[ks], bh1);
            }
        }
        __syncthreads();
    }

    // ---- epilogue: normalize, split hi/lo, store
    const float i0 = 1.f / l0, i1 = 1.f / l1;
#pragma unroll
    for (int nt = 0; nt < 16; nt++) {
        const int d = nt * 8 + 2 * t4;
        unsigned uh, ul;
        pack_hl(O[nt][0] * i0, O[nt][1] * i0, uh, ul);
        const size_t o0 = (size_t)r0g * HID + h * HD + d;
        *(unsigned*)&g_attn_hi[o0] = uh;
        *(unsigned*)&g_attn_lo[o0] = ul;
        pack_hl(O[nt][2] * i1, O[nt][3] * i1, uh, ul);
        const size_t o1 = (size_t)(r0g + 8) * HID + h * HD + d;
        *(unsigned*)&g_attn_hi[o1] = uh;
        *(unsigned*)&g_attn_lo[o1] = ul;
    }
}

// ------------------------- RoPE (in-place, fp32 qkv) ------------------------
__global__ void rope_kernel(const int* __restrict__ positions)
{
    const int total = SEQ * 40 * 64;
    int idx = blockIdx.x * blockDim.x + threadIdx.x;
    if (idx >= total) return;
    const int i    = idx & 63;
    const int head = (idx >> 6) % 40;   // 0..31 Q, 32..39 K
    const int s    = idx / (40 * 64);

    float* base = g_qkv + (size_t)s * QKVN +
                  (head < 32 ? head * HD : HID + (head - 32) * HD);

    const double pos = (double)positions[s];
    const double inv_freq = exp(-(double)i * (9.210340371976184 / 64.0));
    const double a = pos * inv_freq;
    const float c  = (float)cos(a);
    const float sn = (float)sin(a);

    const float x1 = base[i];
    const float x2 = base[i + 64];
    base[i]      = x1 * c - x2 * sn;
    base[i + 64] = x2 * c + x1 * sn;
}

// ---------------------------------------------------------------------------
extern "C" void kernel_launch(void* const* d_in, const int* in_sizes, int n_in,
                              void* d_out, int out_size)
{
    const int*   positions = (const int*)d_in[0];
    const float* hidden    = (const float*)d_in[1];
    const float* Wqkv      = (const float*)d_in[2];
    const float* bqkv      = (const float*)d_in[3];
    const float* Wproj     = (const float*)d_in[4];
    const float* bproj     = (const float*)d_in[5];
    float* out = (float*)d_out;

    bf16 *hid_hi, *hid_lo, *wqkvT_hi, *wqkvT_lo, *wprojT_hi, *wprojT_lo;
    bf16 *qkv_hi, *qkv_lo, *vt_hi, *vt_lo, *attn_hi, *attn_lo;
    float *qkv_p;
    cudaGetSymbolAddress((void**)&hid_hi,    g_hid_hi);
    cudaGetSymbolAddress((void**)&hid_lo,    g_hid_lo);
    cudaGetSymbolAddress((void**)&wqkvT_hi,  g_wqkvT_hi);
    cudaGetSymbolAddress((void**)&wqkvT_lo,  g_wqkvT_lo);
    cudaGetSymbolAddress((void**)&wprojT_hi, g_wprojT_hi);
    cudaGetSymbolAddress((void**)&wprojT_lo, g_wprojT_lo);
    cudaGetSymbolAddress((void**)&qkv_p,     g_qkv);
    cudaGetSymbolAddress((void**)&qkv_hi,    g_qkv_hi);
    cudaGetSymbolAddress((void**)&qkv_lo,    g_qkv_lo);
    cudaGetSymbolAddress((void**)&vt_hi,     g_vt_hi);
    cudaGetSymbolAddress((void**)&vt_lo,     g_vt_lo);
    cudaGetSymbolAddress((void**)&attn_hi,   g_attn_hi);
    cudaGetSymbolAddress((void**)&attn_lo,   g_attn_lo);

    const int SMEM_GEMM = 2 * 4 * 128 * KPAD * 2;   // 81920
    cudaFuncSetAttribute(gemm3p, cudaFuncAttributeMaxDynamicSharedMemorySize, SMEM_GEMM);
    cudaFuncSetAttribute(flash_attn, cudaFuncAttributeMaxDynamicSharedMemorySize, SMEM_FLASH);

    const float scale = 1.0f / sqrtf((float)HD);
    const float kl2   = scale * 1.4426950408889634f;

    // 0) splits: hidden (plain), Wqkv/Wproj (transposed)
    {
        size_t n1 = (size_t)SEQ * HID;
        split_f32<<<(unsigned)((n1/4 + 255)/256), 256>>>(hidden, hid_hi, hid_lo, n1);
        dim3 tb(32, 8);
        tsplit_f32<<<dim3(QKVN/32, HID/32, 1), tb>>>(Wqkv, QKVN, 0, wqkvT_hi, wqkvT_lo, HID, 0);
        tsplit_f32<<<dim3(HID/32, HID/32, 1),  tb>>>(Wproj, HID, 0, wprojT_hi, wprojT_lo, HID, 0);
    }

    // 1) QKV projection
    gemm3p<<<dim3(QKVN/128, SEQ/128), 256, SMEM_GEMM>>>(
        HID, hid_hi, hid_lo, HID, wqkvT_hi, wqkvT_lo, HID,
        bqkv, 1.0f, qkv_p, QKVN);

    // 2) RoPE on Q and K
    rope_kernel<<<(SEQ * 40 * 64 + 255) / 256, 256>>>(positions);

    // 3) split qkv; transpose-split V per KV head
    {
        size_t n = (size_t)SEQ * QKVN;
        split_f32<<<(unsigned)((n/4 + 255)/256), 256>>>(qkv_p, qkv_hi, qkv_lo, n);
        dim3 tb(32, 8);
        tsplit_f32<<<dim3(HD/32, SEQ/32, NKVH), tb>>>(
            qkv_p + HID + KVD, QKVN, HD, vt_hi, vt_lo, SEQ, (long long)HD * SEQ);
    }

    // 4) fused flash attention -> attn hi/lo
    flash_attn<<<dim3(16, NQH), 256, SMEM_FLASH>>>(kl2);

    // 5) output projection
    gemm3p<<<dim3(HID/128, SEQ/128), 256, SMEM_GEMM>>>(
        HID, attn_hi, attn_lo, HID, wprojT_hi, wprojT_lo, HID,
        bproj, 1.0f, out, HID);
}